// round 14
// baseline (speedup 1.0000x reference)
#include <cuda_runtime.h>
#include <cuda_bf16.h>

#define NUM_POINTS 16
#define IN_CHANNELS 64
#define OUT_CHANNELS 256
#define NUM_STEPS 3
#define THREADS 256
#define WARPS_PER_BLOCK (THREADS / 32)
#define ROW_PAIRS 2   // each warp: 2 pairs of rows = 4 rows

// Accurate fast tanh: t = 1 - 2/(exp(2x)+1), via ex2.approx (~2ulp) + rcp.approx (~1ulp).
__device__ __forceinline__ float tanh_fast(float x) {
    const float LOG2E_X2 = 2.8853900817779268f;  // 2*log2(e)
    float e, r;
    float z = x * LOG2E_X2;
    asm("ex2.approx.f32 %0, %1;" : "=f"(e) : "f"(z));
    float d = e + 1.0f;
    asm("rcp.approx.f32 %0, %1;" : "=f"(r) : "f"(d));
    return fmaf(-2.0f, r, 1.0f);
}

// LUT lives in registers across lanes: lane i holds entry (i & 15).
// Lookup = two independent warp shuffles on the bin index.
__device__ __forceinline__ float iterate_g(float x, float l0, float l1) {
    // 8+8t in [0,16]; fmaf(t, 8, 8 + 1.5*2^23) deposits round-nearest-even
    // integer in the low mantissa bits (single rounding).
    const float MAGIC = 12582912.0f + 8.0f;  // 1.5*2^23 + 8
#pragma unroll
    for (int s = 0; s < NUM_STEPS; s++) {
        float t = tanh_fast(x);
        int pos = __float_as_int(fmaf(t, 8.0f, MAGIC)) & 31;
        pos = min(pos, NUM_POINTS - 1);
        float c0 = __shfl_sync(0xFFFFFFFFu, l0, pos);
        float c1 = __shfl_sync(0xFFFFFFFFu, l1, pos);
        x = fmaf(t, c1, x + c0);
    }
    return x;
}

__global__ __launch_bounds__(THREADS) void functional_flow_kernel(
    const float* __restrict__ data,
    const float* __restrict__ angles,
    const float* __restrict__ velo,
    float* __restrict__ out) {
    int tid  = threadIdx.x;
    int warp = tid >> 5;
    int lane = tid & 31;
    int half = lane >> 4;        // which row of the pair
    int subl = lane & 15;        // lane within the 16-lane row group

    // Each warp owns ROW_PAIRS consecutive row-pairs: rows [base, base+4).
    int base = (blockIdx.x * WARPS_PER_BLOCK + warp) * (2 * ROW_PAIRS);
    int rowA = base + half;          // pair 0
    int rowB = base + 2 + half;      // pair 1

    // Issue both loads up-front (MLP=2); 8 independent chains follow.
    const float4* dp = reinterpret_cast<const float4*>(data);
    float4 dA = dp[rowA * (IN_CHANNELS / 4) + subl];
    float4 dB = dp[rowB * (IN_CHANNELS / 4) + subl];

    // Register LUT entry for this lane (replicated across both half-warps).
    float a = angles[subl];
    float v = velo[subl] * (1.0f / (float)NUM_STEPS);
    float l0 = v * __cosf(a);
    float l1 = v * __sinf(a);

    // Eight independent chains (ILP=8), zero smem, zero barriers.
    float sA = (iterate_g(dA.x, l0, l1) + iterate_g(dA.y, l0, l1)) +
               (iterate_g(dA.z, l0, l1) + iterate_g(dA.w, l0, l1));
    float sB = (iterate_g(dB.x, l0, l1) + iterate_g(dB.y, l0, l1)) +
               (iterate_g(dB.z, l0, l1) + iterate_g(dB.w, l0, l1));

    // Sum across the 16-lane row groups (two independent reductions).
#pragma unroll
    for (int off = 8; off > 0; off >>= 1) {
        sA += __shfl_xor_sync(0xFFFFFFFFu, sA, off);
        sB += __shfl_xor_sync(0xFFFFFFFFu, sB, off);
    }

    // Broadcast each row sum to its 256 out channels: 4x float4 per row.
    float4 vA = make_float4(sA, sA, sA, sA);
    float4 vB = make_float4(sB, sB, sB, sB);
    float4* opA = reinterpret_cast<float4*>(out) + (size_t)rowA * (OUT_CHANNELS / 4);
    float4* opB = reinterpret_cast<float4*>(out) + (size_t)rowB * (OUT_CHANNELS / 4);
#pragma unroll
    for (int j = 0; j < 4; j++) {
        opA[j * 16 + subl] = vA;
        opB[j * 16 + subl] = vB;
    }
}

extern "C" void kernel_launch(void* const* d_in, const int* in_sizes, int n_in,
                              void* d_out, int out_size) {
    const float* data   = (const float*)d_in[0];
    const float* angles = (const float*)d_in[1];
    const float* velo   = (const float*)d_in[2];
    float* out = (float*)d_out;

    int nrows = in_sizes[0] / IN_CHANNELS;                       // 4096
    int rows_per_block = WARPS_PER_BLOCK * 2 * ROW_PAIRS;        // 32
    int blocks = (nrows + rows_per_block - 1) / rows_per_block;  // 128

    functional_flow_kernel<<<blocks, THREADS>>>(data, angles, velo, out);
}